// round 13
// baseline (speedup 1.0000x reference)
#include <cuda_runtime.h>
#include <cuda_bf16.h>
#include <cstdint>

#define BATCH 2
#define HW 65536
#define NPIX 131072
#define NSPIX 256
#define FEAT 20
#define AFF_OFF 0
#define CID_OFF 1179648
#define CENT_OFF 1769472
#define OUT_TOTAL 1779712

#define PROW 258
#define PIMG (PROW * PROW)
#define NPAD (BATCH * PIMG)
#define CP1 1088
#define CP2 512

// ---------------- device scratch ----------------
__device__ float g_h1[512 * NPIX];   // conv1 pre-BN, CHW
__device__ float g_h2[128 * NPIX];   // conv2 pre-BN, CHW
__device__ float g_pf[FEAT * NPIX];
__device__ float g_scale[1024];
__device__ float g_shift[1024];
__device__ float g_cent[BATCH * FEAT * NSPIX];
__device__ float g_part[BATCH * NSPIX * 9 * 21];
__device__ unsigned int g_barcnt;
__device__ __align__(1024) __nv_bfloat16 g_X1h[(size_t)NPAD * CP1];
__device__ __align__(1024) __nv_bfloat16 g_X2h[(size_t)NPAD * CP2];
__device__ __align__(1024) __nv_bfloat16 g_W1h[512 * 9 * CP1];
__device__ __align__(1024) __nv_bfloat16 g_W2h[128 * 9 * CP2];

// ---------------- PTX helpers (sm_80-baseline only) ----------------
__device__ __forceinline__ uint32_t s2u(const void* p) {
    uint32_t a;
    asm("{ .reg .u64 t; cvta.to.shared.u64 t, %1; cvt.u32.u64 %0, t; }" : "=r"(a) : "l"(p));
    return a;
}
__device__ __forceinline__ void cpa16(uint32_t s, const void* g) {
    asm volatile("cp.async.cg.shared.global [%0], [%1], 16;" ::"r"(s), "l"(g));
}
// L1-caching variant: A tiles are shared by the 2 co-resident CTAs (bids i, i+148 share blockIdx.y)
__device__ __forceinline__ void cpa16ca(uint32_t s, const void* g) {
    asm volatile("cp.async.ca.shared.global [%0], [%1], 16;" ::"r"(s), "l"(g));
}
#define CPA_COMMIT() asm volatile("cp.async.commit_group;" ::: "memory")
#define CPA_WAIT1() asm volatile("cp.async.wait_group 1;" ::: "memory")
#define CPA_WAIT0() asm volatile("cp.async.wait_group 0;" ::: "memory")
__device__ __forceinline__ void ldm4(uint32_t* r, uint32_t a) {
    asm volatile("ldmatrix.sync.aligned.m8n8.x4.shared.b16 {%0,%1,%2,%3}, [%4];"
                 : "=r"(r[0]), "=r"(r[1]), "=r"(r[2]), "=r"(r[3])
                 : "r"(a));
}
__device__ __forceinline__ void ldm2(uint32_t* r, uint32_t a) {
    asm volatile("ldmatrix.sync.aligned.m8n8.x2.shared.b16 {%0,%1}, [%2];"
                 : "=r"(r[0]), "=r"(r[1])
                 : "r"(a));
}
__device__ __forceinline__ void mma16816(float* c, const uint32_t* a, const uint32_t* b) {
    asm volatile(
        "mma.sync.aligned.m16n8k16.row.col.f32.bf16.bf16.f32 "
        "{%0,%1,%2,%3}, {%4,%5,%6,%7}, {%8,%9}, {%0,%1,%2,%3};"
        : "+f"(c[0]), "+f"(c[1]), "+f"(c[2]), "+f"(c[3])
        : "r"(a[0]), "r"(a[1]), "r"(a[2]), "r"(a[3]), "r"(b[0]), "r"(b[1]));
}

// ================= bf16 mma.sync implicit-conv GEMM (R5/R9 mainloop, FROZEN) =================
template <int CP>
__global__ void __launch_bounds__(256) mma_gemm(
    const __nv_bfloat16* __restrict__ Wh, const __nv_bfloat16* __restrict__ Xh,
    float* __restrict__ Out) {
    constexpr int CB = CP / 32, KT = 9 * CB;
    extern __shared__ char smraw[];
    const uint32_t sb = s2u(smraw);
    const int tid = threadIdx.x;
    const int nt = blockIdx.x, m0 = blockIdx.y * 128;
    const int b = nt >> 9, y = (nt >> 1) & 255, xh = (nt & 1) * 128;
    const int pix0 = b * HW + y * 256 + xh;
    const int lane = tid & 31, wid = tid >> 5;
    const int mw = wid & 1, nw = wid >> 1;
    const int row = tid >> 1, half = tid & 1;
    const size_t gA0 = (size_t)(m0 + row) * (9 * CP);

    float acc[4][4][4];
#pragma unroll
    for (int i = 0; i < 4; i++)
#pragma unroll
        for (int j = 0; j < 4; j++)
#pragma unroll
            for (int k = 0; k < 4; k++) acc[i][j][k] = 0.f;

    auto issue = [&](int kt, int s) {
        const int tap = kt / CB, cb = kt - tap * CB;
        const uint32_t st = sb + s * 20480;
        const size_t ga = gA0 + tap * CP + cb * 32 + half * 16;
        const uint32_t sa = st + row * 80 + half * 32;
        cpa16ca(sa, Wh + ga);
        cpa16ca(sa + 16, Wh + ga + 8);
        const int pb = b * PIMG + (y + tap / 3) * PROW + tap % 3 + xh;
        const size_t gb = (size_t)(pb + row) * CP + cb * 32 + half * 16;
        const uint32_t so = st + 10240 + row * 80 + half * 32;
        cpa16(so, Xh + gb);
        cpa16(so + 16, Xh + gb + 8);
    };

    issue(0, 0);
    CPA_COMMIT();
    for (int kt = 0; kt < KT; kt++) {
        if (kt + 1 < KT) {
            issue(kt + 1, (kt + 1) & 1);
            CPA_COMMIT();
            CPA_WAIT1();
        } else {
            CPA_WAIT0();
        }
        __syncthreads();
        {
            const uint32_t st = sb + (kt & 1) * 20480;
            const uint32_t aA = st + (mw * 64 + (lane & 15)) * 80 + ((lane >> 4) << 4);
            const uint32_t aB = st + 10240 + (nw * 32 + (lane & 7)) * 80 + (((lane >> 3) & 1) << 4);
#pragma unroll
            for (int ks = 0; ks < 2; ks++) {
                uint32_t ah[4][4], bh[4][2];
#pragma unroll
                for (int mf = 0; mf < 4; mf++) ldm4(ah[mf], aA + mf * (16 * 80) + ks * 32);
#pragma unroll
                for (int nf = 0; nf < 4; nf++) ldm2(bh[nf], aB + nf * (8 * 80) + ks * 32);
#pragma unroll
                for (int mf = 0; mf < 4; mf++)
#pragma unroll
                    for (int nf = 0; nf < 4; nf++) mma16816(acc[mf][nf], ah[mf], bh[nf]);
            }
        }
        __syncthreads();
    }

    const int gid = lane >> 2, tig = lane & 3;
#pragma unroll
    for (int mf = 0; mf < 4; mf++) {
        const int m = m0 + mw * 64 + mf * 16 + gid;
        float* bp = Out + (size_t)m * NPIX + pix0 + nw * 32 + tig * 2;
#pragma unroll
        for (int nf = 0; nf < 4; nf++) {
            *(float2*)(bp + nf * 8) = make_float2(acc[mf][nf][0], acc[mf][nf][1]);
            *(float2*)(bp + nf * 8 + (size_t)8 * NPIX) = make_float2(acc[mf][nf][2], acc[mf][nf][3]);
        }
    }
}

// ---------------- pack input CHW fp32 -> halo NHWC bf16 ----------------
__global__ void pack_x(const float* __restrict__ src, __nv_bfloat16* __restrict__ dh,
                       int Creal, int CPv, size_t strC, size_t strB, int bnrelu) {
    __shared__ float sm[64][33];
    const int tid = threadIdx.x;
    const int p0 = blockIdx.x * 32;
    const int c0 = blockIdx.y * 64;
    const int b = p0 >> 16, pin = p0 & 0xFFFF;
    {
        const int px = tid & 31, cl = tid >> 5;
#pragma unroll
        for (int i = 0; i < 8; i++) {
            int c = c0 + cl + i * 8;
            float v = 0.f;
            if (c < Creal) {
                v = src[(size_t)c * strC + (size_t)b * strB + pin + px];
                if (bnrelu) v = fmaxf(fmaf(v, g_scale[c], g_shift[c]), 0.f);
            }
            sm[cl + i * 8][px] = v;
        }
    }
    __syncthreads();
    const int px = tid >> 3, jc = tid & 7;
    const int p = p0 + px, pi = p & 0xFFFF;
    const size_t pp = (size_t)(p >> 16) * PIMG + (size_t)((pi >> 8) + 1) * PROW + (pi & 255) + 1;
    __nv_bfloat16 h8[8];
#pragma unroll
    for (int i = 0; i < 8; i++) h8[i] = __float2bfloat16(sm[jc * 8 + i][px]);
    *(int4*)&dh[pp * CPv + c0 + jc * 8] = *(int4*)h8;
}

// ---------------- pack weights OIHW -> [Mpad][tap][CP] bf16 ----------------
__global__ void pack_w(const float* __restrict__ W, __nv_bfloat16* __restrict__ Wh,
                       int Mreal, int Cin, int CPv, int Mpad) {
    const int idx = blockIdx.x * 256 + threadIdx.x;
    const int cp8 = CPv >> 3;
    if (idx >= Mpad * 9 * cp8) return;
    const int j8 = idx % cp8;
    const int rest = idx / cp8;
    const int tap = rest % 9, m = rest / 9;
    __nv_bfloat16 h8[8];
#pragma unroll
    for (int i = 0; i < 8; i++) {
        int c = j8 * 8 + i;
        float v = (m < Mreal && c < Cin) ? W[((size_t)m * Cin + c) * 9 + tap] : 0.f;
        h8[i] = __float2bfloat16(v);
    }
    *(int4*)&Wh[((size_t)m * 9 + tap) * CPv + j8 * 8] = *(int4*)h8;
}

// ================= fp32 SIMT conv (conv3, R9-identical) =================
__device__ __forceinline__ unsigned long long ffma2(unsigned long long a, unsigned long long b,
                                                    unsigned long long c) {
    asm("fma.rn.f32x2 %0, %1, %2, %3;" : "=l"(c) : "l"(a), "l"(b), "l"(c));
    return c;
}
__device__ __forceinline__ unsigned long long dup2(float a) {
    unsigned long long r;
    asm("mov.b64 %0, {%1, %1};" : "=l"(r) : "f"(a));
    return r;
}
__device__ __forceinline__ float2 unpack2(unsigned long long v) {
    float2 r;
    asm("mov.b64 {%0, %1}, %2;" : "=f"(r.x), "=f"(r.y) : "l"(v));
    return r;
}
template <int BM, int BN, int BK, int TM, int TN>
__global__ void __launch_bounds__(256)
conv_gemm(const float* __restrict__ A, const float* __restrict__ X, float* __restrict__ Out,
          int M, int Cin, int sB, int sC) {
    constexpr int PAD = 4;
    const int K = Cin * 9;
    const int KT = (K + BK - 1) / BK;
    const int n0 = blockIdx.x * BN;
    const int m0 = blockIdx.y * BM;
    const int b = n0 >> 16;
    const int yy = (n0 >> 8) & 0xFF;
    const int x0 = n0 & 0xFF;
    __shared__ float As[2][BK][BM + PAD];
    __shared__ float Bs[2][BK][BN];
    const int tid = threadIdx.x;
    constexpr int NTX = BN / TN;
    const int ty = tid / NTX, tx = tid % NTX;
    constexpr int APL = BM * BK / 256;
    constexpr int BPL = BN * BK / 256;
    float aReg[APL], bReg[BPL];
    auto loadA = [&](int kt) {
#pragma unroll
        for (int i = 0; i < APL; i++) {
            int e = tid + i * 256;
            int m = e / BK, kk = e % BK;
            int kg = kt * BK + kk;
            aReg[i] = (m0 + m < M && kg < K) ? A[(m0 + m) * K + kg] : 0.f;
        }
    };
    auto loadB = [&](int kt) {
#pragma unroll
        for (int i = 0; i < BPL; i++) {
            int e = tid + i * 256;
            int kk = e / BN, j = e % BN;
            int kg = kt * BK + kk;
            float v = 0.f;
            if (kg < K) {
                int ci = kg / 9;
                int r9 = kg - ci * 9;
                int dy = r9 / 3 - 1, dx = r9 % 3 - 1;
                int gy = yy + dy, gx = x0 + j + dx;
                if ((unsigned)gy < 256u && (unsigned)gx < 256u)
                    v = X[b * sB + ci * sC + (gy << 8) + gx];
            }
            bReg[i] = v;
        }
    };
    auto storeS = [&](int buf) {
#pragma unroll
        for (int i = 0; i < APL; i++) {
            int e = tid + i * 256;
            As[buf][e % BK][e / BK] = aReg[i];
        }
#pragma unroll
        for (int i = 0; i < BPL; i++) {
            int e = tid + i * 256;
            Bs[buf][e / BN][e % BN] = bReg[i];
        }
    };
    unsigned long long acc[TM][TN / 2];
#pragma unroll
    for (int i = 0; i < TM; i++)
#pragma unroll
        for (int j = 0; j < TN / 2; j++) acc[i][j] = 0ull;
    loadA(0);
    loadB(0);
    storeS(0);
    __syncthreads();
    for (int kt = 0; kt < KT; kt++) {
        int buf = kt & 1;
        if (kt + 1 < KT) {
            loadA(kt + 1);
            loadB(kt + 1);
        }
#pragma unroll
        for (int kk = 0; kk < BK; kk++) {
            float av[TM];
            unsigned long long bv[TN / 2];
#pragma unroll
            for (int i = 0; i < TM; i++) av[i] = As[buf][kk][ty * TM + i];
            const unsigned long long* bp =
                reinterpret_cast<const unsigned long long*>(&Bs[buf][kk][tx * TN]);
#pragma unroll
            for (int j = 0; j < TN / 2; j++) bv[j] = bp[j];
#pragma unroll
            for (int i = 0; i < TM; i++) {
                unsigned long long a2 = dup2(av[i]);
#pragma unroll
                for (int j = 0; j < TN / 2; j++) acc[i][j] = ffma2(a2, bv[j], acc[i][j]);
            }
        }
        if (kt + 1 < KT) storeS(buf ^ 1);
        __syncthreads();
    }
#pragma unroll
    for (int i = 0; i < TM; i++) {
        int m = m0 + ty * TM + i;
        if (m < M) {
            float2* op = reinterpret_cast<float2*>(Out + (size_t)m * NPIX + n0 + tx * TN);
#pragma unroll
            for (int j = 0; j < TN / 2; j++) op[j] = unpack2(acc[i][j]);
        }
    }
}

// ---------------- BatchNorm (R9-identical) ----------------
__global__ void bn_stats(const float* __restrict__ X, const float* __restrict__ gamma,
                         const float* __restrict__ beta) {
    int c = blockIdx.x;
    const float* p = X + (size_t)c * NPIX;
    float s = 0.f, s2 = 0.f;
    for (int i = threadIdx.x; i < NPIX; i += 256) {
        float v = p[i];
        s += v;
        s2 += v * v;
    }
    __shared__ float rs[8], rs2[8];
#pragma unroll
    for (int o = 16; o > 0; o >>= 1) {
        s += __shfl_down_sync(~0u, s, o);
        s2 += __shfl_down_sync(~0u, s2, o);
    }
    if ((threadIdx.x & 31) == 0) {
        rs[threadIdx.x >> 5] = s;
        rs2[threadIdx.x >> 5] = s2;
    }
    __syncthreads();
    if (threadIdx.x == 0) {
        float S = 0.f, S2 = 0.f;
#pragma unroll
        for (int w = 0; w < 8; w++) {
            S += rs[w];
            S2 += rs2[w];
        }
        float mu = S * (1.f / NPIX);
        float var = S2 * (1.f / NPIX) - mu * mu;
        float inv = rsqrtf(var + 1e-5f);
        float sc = gamma[c] * inv;
        g_scale[c] = sc;
        g_shift[c] = beta[c] - mu * sc;
    }
}
__global__ void bn_apply(float* __restrict__ X, int n) {
    int i = blockIdx.x * 256 + threadIdx.x;
    if (i < n) {
        int c = i >> 17;
        X[i] = fmaxf(fmaf(X[i], g_scale[c], g_shift[c]), 0.f);
    }
}

// ================= SSN =================
__global__ void fill_pf(const float* __restrict__ x, const float* __restrict__ coords) {
    int i = blockIdx.x * 256 + threadIdx.x;
    if (i >= NPIX) return;
    int b = i >> 16, p = i & 0xFFFF;
#pragma unroll
    for (int c = 0; c < 3; c++) g_pf[(15 + c) * NPIX + i] = x[b * 3 * HW + c * HW + p];
    g_pf[18 * NPIX + i] = coords[b * 2 * HW + p];
    g_pf[19 * NPIX + i] = coords[b * 2 * HW + HW + p];
}
__global__ void cent_init() {
    if (blockIdx.x == 0 && threadIdx.x == 0) g_barcnt = 0;  // reset SSN grid barrier
    int blk = blockIdx.x;
    int b = blk >> 8, s = blk & 255;
    int sr = s >> 4, sc = s & 15;
    int ti = threadIdx.x;
    int ly = ti >> 4, lx = ti & 15;
    int p = ((sr * 16 + ly) << 8) + sc * 16 + lx;
    int base = b * HW + p;
    __shared__ float red[FEAT][8];
    int warp = ti >> 5, lane = ti & 31;
#pragma unroll
    for (int c = 0; c < FEAT; c++) {
        float v = g_pf[c * NPIX + base];
#pragma unroll
        for (int o = 16; o > 0; o >>= 1) v += __shfl_down_sync(~0u, v, o);
        if (lane == 0) red[c][warp] = v;
    }
    __syncthreads();
    if (ti < FEAT) {
        float S = 0.f;
#pragma unroll
        for (int w = 0; w < 8; w++) S += red[ti][w];
        g_cent[b * (FEAT * NSPIX) + ti * NSPIX + s] = S * (1.f / 256.f);
    }
}

// Persistent 10-iteration SSN: 512 CTAs, all co-resident (launch_bounds(256,4) ->
// <=64 regs, 26.2KB smem -> >=4 CTAs/SM -> 592 slots >= 512). Grid barrier via counter.
__device__ __forceinline__ void gbar(unsigned int target) {
    __syncthreads();
    if (threadIdx.x == 0) {
        __threadfence();
        atomicAdd(&g_barcnt, 1u);
        while (*((volatile unsigned int*)&g_barcnt) < target) {
        }
    }
    __syncthreads();
    __threadfence();
}

__global__ void __launch_bounds__(256, 4) ssn_loop(float* __restrict__ aff_out) {
    const int blk = blockIdx.x;
    const int b = blk >> 8, cell = blk & 255;
    const int cr = cell >> 4, cc = cell & 15;
    const int ti = threadIdx.x;
    const int ly = ti >> 4, lx = ti & 15;
    const int y = cr * 16 + ly, x = cc * 16 + lx;
    const int p = (y << 8) + x;
    __shared__ float scent[FEAT * NSPIX];
    __shared__ float red[9 * 21 * 8];
    const int warp = ti >> 5, lane = ti & 31;

    float f[FEAT];
#pragma unroll
    for (int c = 0; c < FEAT; c++) f[c] = g_pf[c * NPIX + b * HW + p];

    // candidate table (loop-invariant)
    int sk[9];
    bool valid[9];
#pragma unroll
    for (int k = 0; k < 9; k++) {
        int nr = cr + k / 3 - 1, nc = cc + k % 3 - 1;
        valid[k] = ((unsigned)nr < 16u) && ((unsigned)nc < 16u);
        sk[k] = min(max(nr, 0), 15) * 16 + min(max(nc, 0), 15);
    }

    unsigned int bar = 0;
    for (int it = 0; it < 10; it++) {
        for (int i = ti; i < FEAT * NSPIX; i += 256) scent[i] = g_cent[b * (FEAT * NSPIX) + i];
        __syncthreads();

        float w[9];
        float mx = -1e30f;
#pragma unroll
        for (int k = 0; k < 9; k++) {
            float d = 0.f;
#pragma unroll
            for (int c = 0; c < FEAT; c++) {
                float t = f[c] - scent[c * NSPIX + sk[k]];
                d = fmaf(t, t, d);
            }
            w[k] = -d;
            if (valid[k]) mx = fmaxf(mx, w[k]);
        }
        float sum = 0.f;
#pragma unroll
        for (int k = 0; k < 9; k++) {
            float e = valid[k] ? expf(w[k] - mx) : 0.f;
            w[k] = e;
            sum += e;
        }
        float inv = 1.f / sum;
#pragma unroll
        for (int k = 0; k < 9; k++) {
            w[k] *= inv;
            if (it == 9) aff_out[b * (9 * HW) + k * HW + p] = w[k];
        }

        __syncthreads();  // scent reads done before red reuse is irrelevant, but keep order
#pragma unroll
        for (int k = 0; k < 9; k++) {
#pragma unroll
            for (int c = 0; c < 21; c++) {
                float v = (c < 20) ? w[k] * f[c] : w[k];
#pragma unroll
                for (int o = 16; o > 0; o >>= 1) v += __shfl_down_sync(~0u, v, o);
                if (lane == 0) red[(k * 21 + c) * 8 + warp] = v;
            }
        }
        __syncthreads();
        if (ti < 189) {
            float S = 0.f;
#pragma unroll
            for (int wv = 0; wv < 8; wv++) S += red[ti * 8 + wv];
            g_part[b * (NSPIX * 189) + cell * 189 + ti] = S;
        }

        bar += 512;
        gbar(bar);  // all g_part visible

        // centroid update: this CTA computes entries [blk*20, blk*20+20)
        if (ti < 20) {
            int t = blk * 20 + ti;
            int bb = t / (FEAT * NSPIX);
            int r = t % (FEAT * NSPIX);
            int c = r >> 8, s = r & 255;
            int sr = s >> 4, scol = s & 15;
            float num = 0.f, den = 0.f;
#pragma unroll
            for (int k = 0; k < 9; k++) {
                int rr = sr - (k / 3 - 1), cc2 = scol - (k % 3 - 1);
                if ((unsigned)rr < 16u && (unsigned)cc2 < 16u) {
                    const float* pp =
                        &g_part[bb * (NSPIX * 189) + (rr * 16 + cc2) * 189 + k * 21];
                    num += pp[c];
                    den += pp[20];
                }
            }
            g_cent[t] = num / (den + 1e-16f);
        }
        bar += 512;
        gbar(bar);  // all g_cent visible
    }
}

__global__ void write_tail(float* __restrict__ out) {
    int i = blockIdx.x * 256 + threadIdx.x;
    if (i < 9 * HW) {
        int k = i >> 16, p = i & 0xFFFF;
        int y = p >> 8, x = p & 255;
        int r = min(max((y >> 4) + k / 3 - 1, 0), 15);
        int c = min(max((x >> 4) + k % 3 - 1, 0), 15);
        out[CID_OFF + i] = (float)(r * 16 + c);
    }
    if (i < BATCH * FEAT * NSPIX) out[CENT_OFF + i] = g_cent[i];
}
__global__ void zero_out(float* __restrict__ out, int n) {
    int i = blockIdx.x * 256 + threadIdx.x;
    if (i < n) out[i] = 0.f;
}

// ================= launch =================
extern "C" void kernel_launch(void* const* d_in, const int* in_sizes, int n_in,
                              void* d_out, int out_size) {
    const float* x = (const float*)d_in[0];
    const float* coords = (const float*)d_in[1];
    const float* feats = (const float*)d_in[2];
    const float* W1 = (const float*)d_in[3];
    const float* g1 = (const float*)d_in[4];
    const float* b1 = (const float*)d_in[5];
    const float* W2 = (const float*)d_in[6];
    const float* g2 = (const float*)d_in[7];
    const float* b2 = (const float*)d_in[8];
    const float* W3 = (const float*)d_in[9];
    const float* g3 = (const float*)d_in[10];
    const float* b3 = (const float*)d_in[11];
    float* out = (float*)d_out;
    if (out_size < OUT_TOTAL) {
        zero_out<<<(out_size + 255) / 256, 256>>>(out, out_size);
        return;
    }
    float *h1p, *h2p, *pfp;
    __nv_bfloat16 *w1h, *w2h, *x1h, *x2h;
    cudaGetSymbolAddress((void**)&h1p, g_h1);
    cudaGetSymbolAddress((void**)&h2p, g_h2);
    cudaGetSymbolAddress((void**)&pfp, g_pf);
    cudaGetSymbolAddress((void**)&w1h, g_W1h);
    cudaGetSymbolAddress((void**)&w2h, g_W2h);
    cudaGetSymbolAddress((void**)&x1h, g_X1h);
    cudaGetSymbolAddress((void**)&x2h, g_X2h);

    const int SMEM = 2 * 20480;
    cudaFuncSetAttribute(mma_gemm<CP1>, cudaFuncAttributeMaxDynamicSharedMemorySize, SMEM);
    cudaFuncSetAttribute(mma_gemm<CP2>, cudaFuncAttributeMaxDynamicSharedMemorySize, SMEM);

    // weight + input packs
    pack_w<<<(512 * 9 * (CP1 / 8) + 255) / 256, 256>>>(W1, w1h, 500, 1029, CP1, 512);
    pack_w<<<(128 * 9 * (CP2 / 8) + 255) / 256, 256>>>(W2, w2h, 100, 500, CP2, 128);
    pack_x<<<dim3(NPIX / 32, CP1 / 64), 256>>>(feats, x1h, 1029, CP1,
                                               (size_t)HW, (size_t)1029 * HW, 0);

    // conv1 (tensor mma) -> CHW pre-BN
    mma_gemm<CP1><<<dim3(1024, 4), 256, SMEM>>>(w1h, x1h, h1p);
    bn_stats<<<500, 256>>>(h1p, g1, b1);
    // conv2 input pack with fused BN+ReLU (conv1 scales)
    pack_x<<<dim3(NPIX / 32, CP2 / 64), 256>>>(h1p, x2h, 500, CP2,
                                               (size_t)NPIX, (size_t)HW, 1);

    // conv2 (tensor mma) -> CHW pre-BN
    mma_gemm<CP2><<<dim3(1024, 1), 256, SMEM>>>(w2h, x2h, h2p);
    bn_stats<<<100, 256>>>(h2p, g2, b2);
    bn_apply<<<(100 * NPIX) / 256, 256>>>(h2p, 100 * NPIX);

    // conv3 (SIMT fp32) + BN
    conv_gemm<16, 128, 16, 2, 4><<<dim3(1024, 1), 256>>>(W3, h2p, pfp, 15, 100, HW, NPIX);
    bn_stats<<<15, 256>>>(pfp, g3, b3);
    bn_apply<<<(15 * NPIX) / 256, 256>>>(pfp, 15 * NPIX);

    // SSN: init (also resets grid barrier), then ONE persistent kernel for all 10 iterations
    fill_pf<<<NPIX / 256, 256>>>(x, coords);
    cent_init<<<BATCH * NSPIX, 256>>>();
    ssn_loop<<<BATCH * NSPIX, 256>>>(out + AFF_OFF);
    write_tail<<<(9 * HW + 255) / 256, 256>>>(out);
}

// round 14
// speedup vs baseline: 1.5398x; 1.5398x over previous
#include <cuda_runtime.h>
#include <cuda_bf16.h>
#include <cstdint>

#define BATCH 2
#define HW 65536
#define NPIX 131072
#define NSPIX 256
#define FEAT 20
#define AFF_OFF 0
#define CID_OFF 1179648
#define CENT_OFF 1769472
#define OUT_TOTAL 1779712

#define PROW 258
#define PIMG (PROW * PROW)
#define NPAD (BATCH * PIMG)
#define CP1 1088
#define CP2 512

// ---------------- device scratch ----------------
__device__ float g_h1[512 * NPIX];   // conv1 pre-BN, CHW
__device__ float g_h2[128 * NPIX];   // conv2 pre-BN, CHW
__device__ float g_pf[FEAT * NPIX];
__device__ float g_scale[1024];
__device__ float g_shift[1024];
__device__ float g_cent[BATCH * FEAT * NSPIX];
__device__ float g_part[BATCH * NSPIX * 9 * 21];
__device__ __align__(1024) __nv_bfloat16 g_X1h[(size_t)NPAD * CP1];
__device__ __align__(1024) __nv_bfloat16 g_X2h[(size_t)NPAD * CP2];
__device__ __align__(1024) __nv_bfloat16 g_W1h[512 * 9 * CP1];
__device__ __align__(1024) __nv_bfloat16 g_W2h[128 * 9 * CP2];

// ---------------- PTX helpers (sm_80-baseline only) ----------------
__device__ __forceinline__ uint32_t s2u(const void* p) {
    uint32_t a;
    asm("{ .reg .u64 t; cvta.to.shared.u64 t, %1; cvt.u32.u64 %0, t; }" : "=r"(a) : "l"(p));
    return a;
}
__device__ __forceinline__ void cpa16(uint32_t s, const void* g) {
    asm volatile("cp.async.cg.shared.global [%0], [%1], 16;" ::"r"(s), "l"(g));
}
// L1-caching variant: A tiles are shared by the 2 co-resident CTAs (bids i, i+148 share blockIdx.y)
__device__ __forceinline__ void cpa16ca(uint32_t s, const void* g) {
    asm volatile("cp.async.ca.shared.global [%0], [%1], 16;" ::"r"(s), "l"(g));
}
#define CPA_COMMIT() asm volatile("cp.async.commit_group;" ::: "memory")
#define CPA_WAIT1() asm volatile("cp.async.wait_group 1;" ::: "memory")
#define CPA_WAIT0() asm volatile("cp.async.wait_group 0;" ::: "memory")
__device__ __forceinline__ void ldm4(uint32_t* r, uint32_t a) {
    asm volatile("ldmatrix.sync.aligned.m8n8.x4.shared.b16 {%0,%1,%2,%3}, [%4];"
                 : "=r"(r[0]), "=r"(r[1]), "=r"(r[2]), "=r"(r[3])
                 : "r"(a));
}
__device__ __forceinline__ void ldm2(uint32_t* r, uint32_t a) {
    asm volatile("ldmatrix.sync.aligned.m8n8.x2.shared.b16 {%0,%1}, [%2];"
                 : "=r"(r[0]), "=r"(r[1])
                 : "r"(a));
}
__device__ __forceinline__ void mma16816(float* c, const uint32_t* a, const uint32_t* b) {
    asm volatile(
        "mma.sync.aligned.m16n8k16.row.col.f32.bf16.bf16.f32 "
        "{%0,%1,%2,%3}, {%4,%5,%6,%7}, {%8,%9}, {%0,%1,%2,%3};"
        : "+f"(c[0]), "+f"(c[1]), "+f"(c[2]), "+f"(c[3])
        : "r"(a[0]), "r"(a[1]), "r"(a[2]), "r"(a[3]), "r"(b[0]), "r"(b[1]));
}

// ================= bf16 mma.sync implicit-conv GEMM (R5/R9 mainloop, FROZEN) =================
// BM=128, BN=128, 8 warps (2x4), warp tile 64x32. Out CHW fp32.
// smem rows: 80B stride (64B data = one 32-elem K-chunk + 16B pad) -> conflict-free LDSM.
// Stage = A(10240) + B(10240) = 20480 B, double-buffered, 2 syncs/chunk.
template <int CP>
__global__ void __launch_bounds__(256) mma_gemm(
    const __nv_bfloat16* __restrict__ Wh, const __nv_bfloat16* __restrict__ Xh,
    float* __restrict__ Out) {
    constexpr int CB = CP / 32, KT = 9 * CB;
    extern __shared__ char smraw[];
    const uint32_t sb = s2u(smraw);
    const int tid = threadIdx.x;
    const int nt = blockIdx.x, m0 = blockIdx.y * 128;
    const int b = nt >> 9, y = (nt >> 1) & 255, xh = (nt & 1) * 128;
    const int pix0 = b * HW + y * 256 + xh;
    const int lane = tid & 31, wid = tid >> 5;
    const int mw = wid & 1, nw = wid >> 1;
    const int row = tid >> 1, half = tid & 1;
    const size_t gA0 = (size_t)(m0 + row) * (9 * CP);

    float acc[4][4][4];
#pragma unroll
    for (int i = 0; i < 4; i++)
#pragma unroll
        for (int j = 0; j < 4; j++)
#pragma unroll
            for (int k = 0; k < 4; k++) acc[i][j][k] = 0.f;

    auto issue = [&](int kt, int s) {
        const int tap = kt / CB, cb = kt - tap * CB;
        const uint32_t st = sb + s * 20480;
        const size_t ga = gA0 + tap * CP + cb * 32 + half * 16;
        const uint32_t sa = st + row * 80 + half * 32;
        cpa16ca(sa, Wh + ga);
        cpa16ca(sa + 16, Wh + ga + 8);
        const int pb = b * PIMG + (y + tap / 3) * PROW + tap % 3 + xh;
        const size_t gb = (size_t)(pb + row) * CP + cb * 32 + half * 16;
        const uint32_t so = st + 10240 + row * 80 + half * 32;
        cpa16(so, Xh + gb);
        cpa16(so + 16, Xh + gb + 8);
    };

    issue(0, 0);
    CPA_COMMIT();
    for (int kt = 0; kt < KT; kt++) {
        if (kt + 1 < KT) {
            issue(kt + 1, (kt + 1) & 1);
            CPA_COMMIT();
            CPA_WAIT1();
        } else {
            CPA_WAIT0();
        }
        __syncthreads();
        {
            const uint32_t st = sb + (kt & 1) * 20480;
            const uint32_t aA = st + (mw * 64 + (lane & 15)) * 80 + ((lane >> 4) << 4);
            const uint32_t aB = st + 10240 + (nw * 32 + (lane & 7)) * 80 + (((lane >> 3) & 1) << 4);
#pragma unroll
            for (int ks = 0; ks < 2; ks++) {
                uint32_t ah[4][4], bh[4][2];
#pragma unroll
                for (int mf = 0; mf < 4; mf++) ldm4(ah[mf], aA + mf * (16 * 80) + ks * 32);
#pragma unroll
                for (int nf = 0; nf < 4; nf++) ldm2(bh[nf], aB + nf * (8 * 80) + ks * 32);
#pragma unroll
                for (int mf = 0; mf < 4; mf++)
#pragma unroll
                    for (int nf = 0; nf < 4; nf++) mma16816(acc[mf][nf], ah[mf], bh[nf]);
            }
        }
        __syncthreads();
    }

    const int gid = lane >> 2, tig = lane & 3;
#pragma unroll
    for (int mf = 0; mf < 4; mf++) {
        const int m = m0 + mw * 64 + mf * 16 + gid;
        float* bp = Out + (size_t)m * NPIX + pix0 + nw * 32 + tig * 2;
#pragma unroll
        for (int nf = 0; nf < 4; nf++) {
            *(float2*)(bp + nf * 8) = make_float2(acc[mf][nf][0], acc[mf][nf][1]);
            *(float2*)(bp + nf * 8 + (size_t)8 * NPIX) = make_float2(acc[mf][nf][2], acc[mf][nf][3]);
        }
    }
}

// ---------------- pack input CHW fp32 -> halo NHWC bf16 (R9-identical) ----------------
__global__ void pack_x(const float* __restrict__ src, __nv_bfloat16* __restrict__ dh,
                       int Creal, int CPv, size_t strC, size_t strB, int bnrelu) {
    __shared__ float sm[64][33];
    const int tid = threadIdx.x;
    const int p0 = blockIdx.x * 32;
    const int c0 = blockIdx.y * 64;
    const int b = p0 >> 16, pin = p0 & 0xFFFF;
    {
        const int px = tid & 31, cl = tid >> 5;
#pragma unroll
        for (int i = 0; i < 8; i++) {
            int c = c0 + cl + i * 8;
            float v = 0.f;
            if (c < Creal) {
                v = src[(size_t)c * strC + (size_t)b * strB + pin + px];
                if (bnrelu) v = fmaxf(fmaf(v, g_scale[c], g_shift[c]), 0.f);
            }
            sm[cl + i * 8][px] = v;
        }
    }
    __syncthreads();
    const int px = tid >> 3, jc = tid & 7;
    const int p = p0 + px, pi = p & 0xFFFF;
    const size_t pp = (size_t)(p >> 16) * PIMG + (size_t)((pi >> 8) + 1) * PROW + (pi & 255) + 1;
    __nv_bfloat16 h8[8];
#pragma unroll
    for (int i = 0; i < 8; i++) h8[i] = __float2bfloat16(sm[jc * 8 + i][px]);
    *(int4*)&dh[pp * CPv + c0 + jc * 8] = *(int4*)h8;
}

// ---------------- pack weights OIHW -> [Mpad][tap][CP] bf16 (R9-identical) ----------------
__global__ void pack_w(const float* __restrict__ W, __nv_bfloat16* __restrict__ Wh,
                       int Mreal, int Cin, int CPv, int Mpad) {
    const int idx = blockIdx.x * 256 + threadIdx.x;
    const int cp8 = CPv >> 3;
    if (idx >= Mpad * 9 * cp8) return;
    const int j8 = idx % cp8;
    const int rest = idx / cp8;
    const int tap = rest % 9, m = rest / 9;
    __nv_bfloat16 h8[8];
#pragma unroll
    for (int i = 0; i < 8; i++) {
        int c = j8 * 8 + i;
        float v = (m < Mreal && c < Cin) ? W[((size_t)m * Cin + c) * 9 + tap] : 0.f;
        h8[i] = __float2bfloat16(v);
    }
    *(int4*)&Wh[((size_t)m * 9 + tap) * CPv + j8 * 8] = *(int4*)h8;
}

// ================= fp32 SIMT conv (conv3, R9-identical) =================
__device__ __forceinline__ unsigned long long ffma2(unsigned long long a, unsigned long long b,
                                                    unsigned long long c) {
    asm("fma.rn.f32x2 %0, %1, %2, %3;" : "=l"(c) : "l"(a), "l"(b), "l"(c));
    return c;
}
__device__ __forceinline__ unsigned long long dup2(float a) {
    unsigned long long r;
    asm("mov.b64 %0, {%1, %1};" : "=l"(r) : "f"(a));
    return r;
}
__device__ __forceinline__ float2 unpack2(unsigned long long v) {
    float2 r;
    asm("mov.b64 {%0, %1}, %2;" : "=f"(r.x), "=f"(r.y) : "l"(v));
    return r;
}
template <int BM, int BN, int BK, int TM, int TN>
__global__ void __launch_bounds__(256)
conv_gemm(const float* __restrict__ A, const float* __restrict__ X, float* __restrict__ Out,
          int M, int Cin, int sB, int sC) {
    constexpr int PAD = 4;
    const int K = Cin * 9;
    const int KT = (K + BK - 1) / BK;
    const int n0 = blockIdx.x * BN;
    const int m0 = blockIdx.y * BM;
    const int b = n0 >> 16;
    const int yy = (n0 >> 8) & 0xFF;
    const int x0 = n0 & 0xFF;
    __shared__ float As[2][BK][BM + PAD];
    __shared__ float Bs[2][BK][BN];
    const int tid = threadIdx.x;
    constexpr int NTX = BN / TN;
    const int ty = tid / NTX, tx = tid % NTX;
    constexpr int APL = BM * BK / 256;
    constexpr int BPL = BN * BK / 256;
    float aReg[APL], bReg[BPL];
    auto loadA = [&](int kt) {
#pragma unroll
        for (int i = 0; i < APL; i++) {
            int e = tid + i * 256;
            int m = e / BK, kk = e % BK;
            int kg = kt * BK + kk;
            aReg[i] = (m0 + m < M && kg < K) ? A[(m0 + m) * K + kg] : 0.f;
        }
    };
    auto loadB = [&](int kt) {
#pragma unroll
        for (int i = 0; i < BPL; i++) {
            int e = tid + i * 256;
            int kk = e / BN, j = e % BN;
            int kg = kt * BK + kk;
            float v = 0.f;
            if (kg < K) {
                int ci = kg / 9;
                int r9 = kg - ci * 9;
                int dy = r9 / 3 - 1, dx = r9 % 3 - 1;
                int gy = yy + dy, gx = x0 + j + dx;
                if ((unsigned)gy < 256u && (unsigned)gx < 256u)
                    v = X[b * sB + ci * sC + (gy << 8) + gx];
            }
            bReg[i] = v;
        }
    };
    auto storeS = [&](int buf) {
#pragma unroll
        for (int i = 0; i < APL; i++) {
            int e = tid + i * 256;
            As[buf][e % BK][e / BK] = aReg[i];
        }
#pragma unroll
        for (int i = 0; i < BPL; i++) {
            int e = tid + i * 256;
            Bs[buf][e / BN][e % BN] = bReg[i];
        }
    };
    unsigned long long acc[TM][TN / 2];
#pragma unroll
    for (int i = 0; i < TM; i++)
#pragma unroll
        for (int j = 0; j < TN / 2; j++) acc[i][j] = 0ull;
    loadA(0);
    loadB(0);
    storeS(0);
    __syncthreads();
    for (int kt = 0; kt < KT; kt++) {
        int buf = kt & 1;
        if (kt + 1 < KT) {
            loadA(kt + 1);
            loadB(kt + 1);
        }
#pragma unroll
        for (int kk = 0; kk < BK; kk++) {
            float av[TM];
            unsigned long long bv[TN / 2];
#pragma unroll
            for (int i = 0; i < TM; i++) av[i] = As[buf][kk][ty * TM + i];
            const unsigned long long* bp =
                reinterpret_cast<const unsigned long long*>(&Bs[buf][kk][tx * TN]);
#pragma unroll
            for (int j = 0; j < TN / 2; j++) bv[j] = bp[j];
#pragma unroll
            for (int i = 0; i < TM; i++) {
                unsigned long long a2 = dup2(av[i]);
#pragma unroll
                for (int j = 0; j < TN / 2; j++) acc[i][j] = ffma2(a2, bv[j], acc[i][j]);
            }
        }
        if (kt + 1 < KT) storeS(buf ^ 1);
        __syncthreads();
    }
#pragma unroll
    for (int i = 0; i < TM; i++) {
        int m = m0 + ty * TM + i;
        if (m < M) {
            float2* op = reinterpret_cast<float2*>(Out + (size_t)m * NPIX + n0 + tx * TN);
#pragma unroll
            for (int j = 0; j < TN / 2; j++) op[j] = unpack2(acc[i][j]);
        }
    }
}

// ---------------- BatchNorm (R9-identical) ----------------
__global__ void bn_stats(const float* __restrict__ X, const float* __restrict__ gamma,
                         const float* __restrict__ beta) {
    int c = blockIdx.x;
    const float* p = X + (size_t)c * NPIX;
    float s = 0.f, s2 = 0.f;
    for (int i = threadIdx.x; i < NPIX; i += 256) {
        float v = p[i];
        s += v;
        s2 += v * v;
    }
    __shared__ float rs[8], rs2[8];
#pragma unroll
    for (int o = 16; o > 0; o >>= 1) {
        s += __shfl_down_sync(~0u, s, o);
        s2 += __shfl_down_sync(~0u, s2, o);
    }
    if ((threadIdx.x & 31) == 0) {
        rs[threadIdx.x >> 5] = s;
        rs2[threadIdx.x >> 5] = s2;
    }
    __syncthreads();
    if (threadIdx.x == 0) {
        float S = 0.f, S2 = 0.f;
#pragma unroll
        for (int w = 0; w < 8; w++) {
            S += rs[w];
            S2 += rs2[w];
        }
        float mu = S * (1.f / NPIX);
        float var = S2 * (1.f / NPIX) - mu * mu;
        float inv = rsqrtf(var + 1e-5f);
        float sc = gamma[c] * inv;
        g_scale[c] = sc;
        g_shift[c] = beta[c] - mu * sc;
    }
}
__global__ void bn_apply(float* __restrict__ X, int n) {
    int i = blockIdx.x * 256 + threadIdx.x;
    if (i < n) {
        int c = i >> 17;
        X[i] = fmaxf(fmaf(X[i], g_scale[c], g_shift[c]), 0.f);
    }
}

// ================= SSN =================
// Applies conv3's BN+ReLU to pf rows 0..14 in-place (replaces bn_apply launch),
// then fills rows 15..19 with image + coords.
__global__ void fill_pf(const float* __restrict__ x, const float* __restrict__ coords) {
    int i = blockIdx.x * 256 + threadIdx.x;
    if (i >= NPIX) return;
    int b = i >> 16, p = i & 0xFFFF;
#pragma unroll
    for (int c = 0; c < 15; c++)
        g_pf[c * NPIX + i] = fmaxf(fmaf(g_pf[c * NPIX + i], g_scale[c], g_shift[c]), 0.f);
#pragma unroll
    for (int c = 0; c < 3; c++) g_pf[(15 + c) * NPIX + i] = x[b * 3 * HW + c * HW + p];
    g_pf[18 * NPIX + i] = coords[b * 2 * HW + p];
    g_pf[19 * NPIX + i] = coords[b * 2 * HW + HW + p];
}
__global__ void cent_init() {
    int blk = blockIdx.x;
    int b = blk >> 8, s = blk & 255;
    int sr = s >> 4, sc = s & 15;
    int ti = threadIdx.x;
    int ly = ti >> 4, lx = ti & 15;
    int p = ((sr * 16 + ly) << 8) + sc * 16 + lx;
    int base = b * HW + p;
    __shared__ float red[FEAT][8];
    int warp = ti >> 5, lane = ti & 31;
#pragma unroll
    for (int c = 0; c < FEAT; c++) {
        float v = g_pf[c * NPIX + base];
#pragma unroll
        for (int o = 16; o > 0; o >>= 1) v += __shfl_down_sync(~0u, v, o);
        if (lane == 0) red[c][warp] = v;
    }
    __syncthreads();
    if (ti < FEAT) {
        float S = 0.f;
#pragma unroll
        for (int w = 0; w < 8; w++) S += red[ti][w];
        g_cent[b * (FEAT * NSPIX) + ti * NSPIX + s] = S * (1.f / 256.f);
    }
}
__global__ void __launch_bounds__(256) ssn_assign(float* __restrict__ aff_out) {
    int blk = blockIdx.x;
    int b = blk >> 8, cell = blk & 255;
    int cr = cell >> 4, cc = cell & 15;
    int ti = threadIdx.x;
    int ly = ti >> 4, lx = ti & 15;
    int y = cr * 16 + ly, x = cc * 16 + lx;
    int p = (y << 8) + x;
    __shared__ float scent[FEAT * NSPIX];
    for (int i = ti; i < FEAT * NSPIX; i += 256) scent[i] = g_cent[b * (FEAT * NSPIX) + i];
    __syncthreads();
    float f[FEAT];
#pragma unroll
    for (int c = 0; c < FEAT; c++) f[c] = g_pf[c * NPIX + b * HW + p];
    float w[9];
    int sk[9];
    bool valid[9];
    float mx = -1e30f;
#pragma unroll
    for (int k = 0; k < 9; k++) {
        int dr = k / 3 - 1, dc = k % 3 - 1;
        int nr = cr + dr, nc = cc + dc;
        valid[k] = ((unsigned)nr < 16u) && ((unsigned)nc < 16u);
        int nrc = min(max(nr, 0), 15), ncc = min(max(nc, 0), 15);
        sk[k] = nrc * 16 + ncc;
        float d = 0.f;
#pragma unroll
        for (int c = 0; c < FEAT; c++) {
            float t = f[c] - scent[c * NSPIX + sk[k]];
            d = fmaf(t, t, d);
        }
        w[k] = -d;
        if (valid[k]) mx = fmaxf(mx, w[k]);
    }
    float sum = 0.f;
#pragma unroll
    for (int k = 0; k < 9; k++) {
        float e = valid[k] ? expf(w[k] - mx) : 0.f;
        w[k] = e;
        sum += e;
    }
    float inv = 1.f / sum;
#pragma unroll
    for (int k = 0; k < 9; k++) {
        w[k] *= inv;
        aff_out[b * (9 * HW) + k * HW + p] = w[k];
    }
    __shared__ float red[9 * 21 * 8];
    int warp = ti >> 5, lane = ti & 31;
#pragma unroll
    for (int k = 0; k < 9; k++) {
#pragma unroll
        for (int c = 0; c < 21; c++) {
            float v = (c < 20) ? w[k] * f[c] : w[k];
#pragma unroll
            for (int o = 16; o > 0; o >>= 1) v += __shfl_down_sync(~0u, v, o);
            if (lane == 0) red[(k * 21 + c) * 8 + warp] = v;
        }
    }
    __syncthreads();
    if (ti < 189) {
        float S = 0.f;
#pragma unroll
        for (int wv = 0; wv < 8; wv++) S += red[ti * 8 + wv];
        g_part[b * (NSPIX * 189) + cell * 189 + ti] = S;
    }
}
__global__ void cent_update() {
    int t = blockIdx.x * 256 + threadIdx.x;
    if (t >= BATCH * FEAT * NSPIX) return;
    int b = t / (FEAT * NSPIX);
    int r = t % (FEAT * NSPIX);
    int c = r >> 8, s = r & 255;
    int sr = s >> 4, scol = s & 15;
    float num = 0.f, den = 0.f;
#pragma unroll
    for (int k = 0; k < 9; k++) {
        int rr = sr - (k / 3 - 1), cc2 = scol - (k % 3 - 1);
        if ((unsigned)rr < 16u && (unsigned)cc2 < 16u) {
            const float* pp = &g_part[b * (NSPIX * 189) + (rr * 16 + cc2) * 189 + k * 21];
            num += pp[c];
            den += pp[20];
        }
    }
    g_cent[t] = num / (den + 1e-16f);
}
__global__ void write_tail(float* __restrict__ out) {
    int i = blockIdx.x * 256 + threadIdx.x;
    if (i < 9 * HW) {
        int k = i >> 16, p = i & 0xFFFF;
        int y = p >> 8, x = p & 255;
        int r = min(max((y >> 4) + k / 3 - 1, 0), 15);
        int c = min(max((x >> 4) + k % 3 - 1, 0), 15);
        out[CID_OFF + i] = (float)(r * 16 + c);
    }
    if (i < BATCH * FEAT * NSPIX) out[CENT_OFF + i] = g_cent[i];
}
__global__ void zero_out(float* __restrict__ out, int n) {
    int i = blockIdx.x * 256 + threadIdx.x;
    if (i < n) out[i] = 0.f;
}

// ================= launch =================
extern "C" void kernel_launch(void* const* d_in, const int* in_sizes, int n_in,
                              void* d_out, int out_size) {
    const float* x = (const float*)d_in[0];
    const float* coords = (const float*)d_in[1];
    const float* feats = (const float*)d_in[2];
    const float* W1 = (const float*)d_in[3];
    const float* g1 = (const float*)d_in[4];
    const float* b1 = (const float*)d_in[5];
    const float* W2 = (const float*)d_in[6];
    const float* g2 = (const float*)d_in[7];
    const float* b2 = (const float*)d_in[8];
    const float* W3 = (const float*)d_in[9];
    const float* g3 = (const float*)d_in[10];
    const float* b3 = (const float*)d_in[11];
    float* out = (float*)d_out;
    if (out_size < OUT_TOTAL) {
        zero_out<<<(out_size + 255) / 256, 256>>>(out, out_size);
        return;
    }
    float *h1p, *h2p, *pfp;
    __nv_bfloat16 *w1h, *w2h, *x1h, *x2h;
    cudaGetSymbolAddress((void**)&h1p, g_h1);
    cudaGetSymbolAddress((void**)&h2p, g_h2);
    cudaGetSymbolAddress((void**)&pfp, g_pf);
    cudaGetSymbolAddress((void**)&w1h, g_W1h);
    cudaGetSymbolAddress((void**)&w2h, g_W2h);
    cudaGetSymbolAddress((void**)&x1h, g_X1h);
    cudaGetSymbolAddress((void**)&x2h, g_X2h);

    const int SMEM = 2 * 20480;
    cudaFuncSetAttribute(mma_gemm<CP1>, cudaFuncAttributeMaxDynamicSharedMemorySize, SMEM);
    cudaFuncSetAttribute(mma_gemm<CP2>, cudaFuncAttributeMaxDynamicSharedMemorySize, SMEM);

    // weight + input packs
    pack_w<<<(512 * 9 * (CP1 / 8) + 255) / 256, 256>>>(W1, w1h, 500, 1029, CP1, 512);
    pack_w<<<(128 * 9 * (CP2 / 8) + 255) / 256, 256>>>(W2, w2h, 100, 500, CP2, 128);
    pack_x<<<dim3(NPIX / 32, CP1 / 64), 256>>>(feats, x1h, 1029, CP1,
                                               (size_t)HW, (size_t)1029 * HW, 0);

    // conv1 (tensor mma) -> CHW pre-BN
    mma_gemm<CP1><<<dim3(1024, 4), 256, SMEM>>>(w1h, x1h, h1p);
    bn_stats<<<500, 256>>>(h1p, g1, b1);
    // conv2 input pack with fused BN+ReLU (conv1 scales)
    pack_x<<<dim3(NPIX / 32, CP2 / 64), 256>>>(h1p, x2h, 500, CP2,
                                               (size_t)NPIX, (size_t)HW, 1);

    // conv2 (tensor mma) -> CHW pre-BN
    mma_gemm<CP2><<<dim3(1024, 1), 256, SMEM>>>(w2h, x2h, h2p);
    bn_stats<<<100, 256>>>(h2p, g2, b2);
    bn_apply<<<(100 * NPIX) / 256, 256>>>(h2p, 100 * NPIX);

    // conv3 (SIMT fp32); its BN+ReLU is applied inside fill_pf
    conv_gemm<16, 128, 16, 2, 4><<<dim3(1024, 1), 256>>>(W3, h2p, pfp, 15, 100, HW, NPIX);
    bn_stats<<<15, 256>>>(pfp, g3, b3);

    // SSN
    fill_pf<<<NPIX / 256, 256>>>(x, coords);
    cent_init<<<BATCH * NSPIX, 256>>>();
    for (int it = 0; it < 10; it++) {
        ssn_assign<<<BATCH * NSPIX, 256>>>(out + AFF_OFF);
        cent_update<<<(BATCH * FEAT * NSPIX + 255) / 256, 256>>>();
    }
    write_tail<<<(9 * HW + 255) / 256, 256>>>(out);
}